// round 4
// baseline (speedup 1.0000x reference)
#include <cuda_runtime.h>
#include <math.h>

constexpr int N_    = 8192;
constexpr int IN_F_ = 512;
constexpr int D_    = 64;
constexpr float NEG_INF_F = -9000000000000000.0f;
constexpr float LRELU_A   = 0.2f;

// Scratch (device globals: no allocation allowed). 16B-aligned for float4 access.
__device__ __align__(16) float g_h[N_ * D_];   // h = input @ W   (8192 x 64)
__device__ float g_attl[N_];                   // h @ a_left
__device__ float g_attr[N_];                   // h @ a_right

// ---------------------------------------------------------------------------
// Phase 1: h = input @ W   (8192x512 @ 512x64, fp32)
// BM=64 rows per CTA, BK=32 k-tile, 256 threads, 4x4 microtile per thread.
// ---------------------------------------------------------------------------
constexpr int BM = 64;
constexpr int BK = 32;

__global__ void __launch_bounds__(256) k_gemm(const float* __restrict__ inp,
                                              const float* __restrict__ W) {
    __shared__ float As[BK][BM + 1];   // pad=1: conflict-free transpose scatter
    __shared__ float Bs[BK][D_];       // W tile (row = 256B, float4-aligned)
    const int tid  = threadIdx.x;
    const int row0 = blockIdx.x * BM;
    const int ty   = tid >> 4;         // 0..15 -> rows ty*4..ty*4+3
    const int tx   = tid & 15;         // cols tx*4..tx*4+3

    float acc[4][4];
#pragma unroll
    for (int i = 0; i < 4; ++i)
#pragma unroll
        for (int j = 0; j < 4; ++j) acc[i][j] = 0.0f;

    for (int k0 = 0; k0 < IN_F_; k0 += BK) {
        __syncthreads();
        // load A tile (64 rows x 32 k), transpose into As[k][row]
        {
            const int r = tid >> 3;            // 0..31
            const int c = (tid & 7) * 4;       // 0..28
#pragma unroll
            for (int rr = 0; rr < BM; rr += 32) {
                float4 v = *(const float4*)(inp + (size_t)(row0 + rr + r) * IN_F_ + k0 + c);
                As[c + 0][rr + r] = v.x;
                As[c + 1][rr + r] = v.y;
                As[c + 2][rr + r] = v.z;
                As[c + 3][rr + r] = v.w;
            }
        }
        // load B tile (32 k x 64 cols)
        {
            const int kk = tid >> 3;           // 0..31
            const int c  = (tid & 7) * 8;      // 0..56
            float4 v0 = *(const float4*)(W + (size_t)(k0 + kk) * D_ + c);
            float4 v1 = *(const float4*)(W + (size_t)(k0 + kk) * D_ + c + 4);
            *(float4*)&Bs[kk][c]     = v0;
            *(float4*)&Bs[kk][c + 4] = v1;
        }
        __syncthreads();
#pragma unroll
        for (int kk = 0; kk < BK; ++kk) {
            // SCALAR loads from As: row stride 260B is not float4-aligned.
            // Within a warp only 2 distinct ty values -> broadcast, no conflicts.
            float a[4];
#pragma unroll
            for (int i = 0; i < 4; ++i) a[i] = As[kk][ty * 4 + i];
            float4 b4 = *(const float4*)&Bs[kk][tx * 4];
            float b[4] = {b4.x, b4.y, b4.z, b4.w};
#pragma unroll
            for (int i = 0; i < 4; ++i)
#pragma unroll
                for (int j = 0; j < 4; ++j)
                    acc[i][j] += a[i] * b[j];
        }
    }
#pragma unroll
    for (int i = 0; i < 4; ++i) {
        float4 v = make_float4(acc[i][0], acc[i][1], acc[i][2], acc[i][3]);
        *(float4*)(g_h + (size_t)(row0 + ty * 4 + i) * D_ + tx * 4) = v;
    }
}

// ---------------------------------------------------------------------------
// Phase 1b: att_l[i] = h[i] . a[0:64],  att_r[i] = h[i] . a[64:128]
// One warp per row.
// ---------------------------------------------------------------------------
__global__ void __launch_bounds__(256) k_att(const float* __restrict__ a) {
    const int warp = threadIdx.x >> 5;
    const int lane = threadIdx.x & 31;
    const int row  = blockIdx.x * 8 + warp;
    const float* hr = g_h + (size_t)row * D_;
    float h0 = hr[lane], h1 = hr[lane + 32];
    float sl = h0 * a[lane]      + h1 * a[lane + 32];
    float sr = h0 * a[64 + lane] + h1 * a[96 + lane];
#pragma unroll
    for (int o = 16; o >= 1; o >>= 1) {
        sl += __shfl_xor_sync(0xffffffffu, sl, o);
        sr += __shfl_xor_sync(0xffffffffu, sr, o);
    }
    if (lane == 0) { g_attl[row] = sl; g_attr[row] = sr; }
}

// ---------------------------------------------------------------------------
// Phase 2: fused masked-softmax attention (flash-style, fp32).
//   RT=32 rows per CTA, TJ=64 j-tile, 256 threads.
//   e_ij = leaky_relu(att_l[i]+att_r[j]) if adj else -9e15
//   online softmax over j; acc += p * h[j]; out = elu(acc / sum)
// ---------------------------------------------------------------------------
constexpr int RT = 32;
constexpr int TJ = 64;

__global__ void __launch_bounds__(256, 2) k_flash(const int* __restrict__ adj,
                                                  float* __restrict__ out) {
    __shared__ __align__(16) float h_s[TJ * D_];        // 16 KB: h tile
    __shared__ __align__(16) float p_s[RT][TJ + 4];     // 8.5 KB (row=272B, 16B-aligned)
    __shared__ float ar_s[TJ];
    __shared__ float al_s[RT];
    __shared__ float m_s[RT];
    __shared__ float scale_s[RT];
    __shared__ float s_s[RT];

    const int tid = threadIdx.x;
    const int i0  = blockIdx.x * RT;

    if (tid < RT) {
        al_s[tid] = g_attl[i0 + tid];
        m_s[tid]  = -3.0e38f;
        s_s[tid]  = 0.0f;
    }

    // e/p-phase mapping: thread owns row er, 8 consecutive j (t = etg*8..etg*8+7)
    const int er  = tid >> 3;      // 0..31
    const int etg = tid & 7;       // 0..7
    // acc-phase mapping: thread owns 2 rows x 4 cols
    const int cg  = tid & 15;      // cols cg*4..cg*4+3
    const int rg  = tid >> 4;      // rows rg*2, rg*2+1
    const int r0  = rg * 2, r1 = rg * 2 + 1;

    float acc[8];
#pragma unroll
    for (int q = 0; q < 8; ++q) acc[q] = 0.0f;

    for (int j0 = 0; j0 < N_; j0 += TJ) {
        __syncthreads();   // previous tile's acc phase done with h_s / p_s
        // cooperative load of h tile (contiguous region: straight float4 copy)
        {
            const float4* src = (const float4*)(g_h + (size_t)j0 * D_);
            float4* dst = (float4*)h_s;
#pragma unroll
            for (int k = 0; k < (TJ * D_ / 4) / 256; ++k)
                dst[tid + k * 256] = src[tid + k * 256];
        }
        if (tid < TJ) ar_s[tid] = g_attr[j0 + tid];
        __syncthreads();   // tile loads visible

        // ---- e phase: 8 elements per thread, coalesced adj reads ----
        const float al = al_s[er];
        const int4* adjp = (const int4*)(adj + (size_t)(i0 + er) * N_ + j0 + etg * 8);
        float e[8];
        float em = -3.0e38f;
#pragma unroll
        for (int q = 0; q < 2; ++q) {
            int4 av = adjp[q];
            int m0 = av.x, m1 = av.y, m2 = av.z, m3 = av.w;
            float v0 = al + ar_s[etg * 8 + q * 4 + 0];
            float v1 = al + ar_s[etg * 8 + q * 4 + 1];
            float v2 = al + ar_s[etg * 8 + q * 4 + 2];
            float v3 = al + ar_s[etg * 8 + q * 4 + 3];
            v0 = (v0 > 0.0f) ? v0 : LRELU_A * v0;
            v1 = (v1 > 0.0f) ? v1 : LRELU_A * v1;
            v2 = (v2 > 0.0f) ? v2 : LRELU_A * v2;
            v3 = (v3 > 0.0f) ? v3 : LRELU_A * v3;
            e[q * 4 + 0] = m0 ? v0 : NEG_INF_F;
            e[q * 4 + 1] = m1 ? v1 : NEG_INF_F;
            e[q * 4 + 2] = m2 ? v2 : NEG_INF_F;
            e[q * 4 + 3] = m3 ? v3 : NEG_INF_F;
        }
#pragma unroll
        for (int q = 0; q < 8; ++q) em = fmaxf(em, e[q]);
        // reduce max over the 8 lanes owning this row (xor<8 stays in group)
#pragma unroll
        for (int o = 4; o >= 1; o >>= 1)
            em = fmaxf(em, __shfl_xor_sync(0xffffffffu, em, o));

        const float m_old = m_s[er];           // all 8 lanes read before any write
        const float m_new = fmaxf(m_old, em);
        const float sc    = __expf(m_old - m_new);   // ==0 on first tile (m_old=-3e38)
        if (etg == 0) { m_s[er] = m_new; scale_s[er] = sc; }

        // ---- p phase ----
        float rsum = 0.0f;
        float p[8];
#pragma unroll
        for (int q = 0; q < 8; ++q) {
            p[q] = __expf(e[q] - m_new);       // masked -> exp(-9e15) -> 0
            rsum += p[q];
        }
        *(float4*)&p_s[er][etg * 8]     = make_float4(p[0], p[1], p[2], p[3]);
        *(float4*)&p_s[er][etg * 8 + 4] = make_float4(p[4], p[5], p[6], p[7]);
#pragma unroll
        for (int o = 4; o >= 1; o >>= 1)
            rsum += __shfl_xor_sync(0xffffffffu, rsum, o);
        if (etg == 0) s_s[er] = s_s[er] * sc + rsum;
        __syncthreads();   // p_s / scale_s visible to acc threads

        // ---- accumulate: acc[r][c] = sc*acc + sum_t p[r][t] * h[t][c] ----
        const float sc0 = scale_s[r0];
        const float sc1 = scale_s[r1];
#pragma unroll
        for (int q = 0; q < 4; ++q) { acc[q] *= sc0; acc[q + 4] *= sc1; }
        const float* pr0 = p_s[r0];
        const float* pr1 = p_s[r1];
#pragma unroll 8
        for (int t = 0; t < TJ; ++t) {
            float4 hv = *(const float4*)(h_s + t * D_ + cg * 4);
            float pa = pr0[t];
            float pb = pr1[t];
            acc[0] += pa * hv.x; acc[1] += pa * hv.y;
            acc[2] += pa * hv.z; acc[3] += pa * hv.w;
            acc[4] += pb * hv.x; acc[5] += pb * hv.y;
            acc[6] += pb * hv.z; acc[7] += pb * hv.w;
        }
    }
    __syncthreads();

    // ---- epilogue: divide by softmax denom, ELU, store ----
    const float inv0 = 1.0f / s_s[r0];
    const float inv1 = 1.0f / s_s[r1];
    float o[8];
#pragma unroll
    for (int q = 0; q < 4; ++q) {
        float v = acc[q] * inv0;
        o[q] = (v > 0.0f) ? v : expm1f(v);
    }
#pragma unroll
    for (int q = 0; q < 4; ++q) {
        float v = acc[q + 4] * inv1;
        o[q + 4] = (v > 0.0f) ? v : expm1f(v);
    }
    *(float4*)(out + (size_t)(i0 + r0) * D_ + cg * 4) = make_float4(o[0], o[1], o[2], o[3]);
    *(float4*)(out + (size_t)(i0 + r1) * D_ + cg * 4) = make_float4(o[4], o[5], o[6], o[7]);
}

// ---------------------------------------------------------------------------
extern "C" void kernel_launch(void* const* d_in, const int* in_sizes, int n_in,
                              void* d_out, int out_size) {
    const float* inp = (const float*)d_in[0];   // (8192, 512) f32
    const int*   adj = (const int*)d_in[1];     // (8192, 8192) i32
    const float* W   = (const float*)d_in[2];   // (512, 64) f32
    const float* a   = (const float*)d_in[3];   // (128, 1) f32
    float* out = (float*)d_out;                 // (8192, 64) f32

    k_gemm <<<N_ / BM, 256>>>(inp, W);
    k_att  <<<N_ / 8,  256>>>(a);
    k_flash<<<N_ / RT, 256>>>(adj, out);
}

// round 7
// speedup vs baseline: 1.4193x; 1.4193x over previous
#include <cuda_runtime.h>
#include <math.h>

constexpr int N_    = 8192;
constexpr int IN_F_ = 512;
constexpr int D_    = 64;
constexpr float LRELU_A = 0.2f;

constexpr int RT     = 128;           // rows per flash CTA
constexpr int TJ     = 64;            // j-tile
constexpr int JSPLIT = 4;             // j-dimension split across CTAs
constexpr int JSL    = N_ / JSPLIT;   // 2048 j per CTA

// Scratch (device globals; no allocation allowed)
__device__ __align__(16) float  g_h[N_ * D_];            // input @ W
__device__ __align__(16) float4 g_rowA[N_];              // (EA, EA2, thr=exp(-al), al)
__device__ __align__(16) float2 g_EBP[N_];               // (EB, EB2)
__device__ __align__(16) float  g_pacc[JSPLIT][N_][D_];  // partial acc (8.4 MB)
__device__ float g_psum[JSPLIT][N_];                     // partial softmax denom

// ---- packed f32x2 helpers ----
__device__ __forceinline__ unsigned long long fma2(unsigned long long a,
                                                   unsigned long long b,
                                                   unsigned long long c) {
    unsigned long long d;
    asm("fma.rn.f32x2 %0, %1, %2, %3;" : "=l"(d) : "l"(a), "l"(b), "l"(c));
    return d;
}
__device__ __forceinline__ unsigned long long pack2(float x) {
    unsigned long long d; unsigned int u = __float_as_uint(x);
    asm("mov.b64 %0, {%1, %1};" : "=l"(d) : "r"(u));
    return d;
}

// ---------------------------------------------------------------------------
// Phase 1: h = input @ W  (unchanged from R4 pass)
// ---------------------------------------------------------------------------
constexpr int BM = 64;
constexpr int BK = 32;

__global__ void __launch_bounds__(256) k_gemm(const float* __restrict__ inp,
                                              const float* __restrict__ W) {
    __shared__ float As[BK][BM + 1];
    __shared__ float Bs[BK][D_];
    const int tid  = threadIdx.x;
    const int row0 = blockIdx.x * BM;
    const int ty   = tid >> 4;
    const int tx   = tid & 15;

    float acc[4][4];
#pragma unroll
    for (int i = 0; i < 4; ++i)
#pragma unroll
        for (int j = 0; j < 4; ++j) acc[i][j] = 0.0f;

    for (int k0 = 0; k0 < IN_F_; k0 += BK) {
        __syncthreads();
        {
            const int r = tid >> 3;
            const int c = (tid & 7) * 4;
#pragma unroll
            for (int rr = 0; rr < BM; rr += 32) {
                float4 v = *(const float4*)(inp + (size_t)(row0 + rr + r) * IN_F_ + k0 + c);
                As[c + 0][rr + r] = v.x;
                As[c + 1][rr + r] = v.y;
                As[c + 2][rr + r] = v.z;
                As[c + 3][rr + r] = v.w;
            }
        }
        {
            const int kk = tid >> 3;
            const int c  = (tid & 7) * 8;
            float4 v0 = *(const float4*)(W + (size_t)(k0 + kk) * D_ + c);
            float4 v1 = *(const float4*)(W + (size_t)(k0 + kk) * D_ + c + 4);
            *(float4*)&Bs[kk][c]     = v0;
            *(float4*)&Bs[kk][c + 4] = v1;
        }
        __syncthreads();
#pragma unroll
        for (int kk = 0; kk < BK; ++kk) {
            float a[4];
#pragma unroll
            for (int i = 0; i < 4; ++i) a[i] = As[kk][ty * 4 + i];
            float4 b4 = *(const float4*)&Bs[kk][tx * 4];
            float b[4] = {b4.x, b4.y, b4.z, b4.w};
#pragma unroll
            for (int i = 0; i < 4; ++i)
#pragma unroll
                for (int j = 0; j < 4; ++j)
                    acc[i][j] += a[i] * b[j];
        }
    }
#pragma unroll
    for (int i = 0; i < 4; ++i) {
        float4 v = make_float4(acc[i][0], acc[i][1], acc[i][2], acc[i][3]);
        *(float4*)(g_h + (size_t)(row0 + ty * 4 + i) * D_ + tx * 4) = v;
    }
}

// ---------------------------------------------------------------------------
// Phase 1b: per-node attention scalars + their exponentials.
//   al = h.a_left, ar = h.a_right
//   g_rowA = (exp(al), exp(0.2 al), exp(-al), al);  g_EBP = (exp(ar), exp(0.2 ar))
// ---------------------------------------------------------------------------
__global__ void __launch_bounds__(256) k_att(const float* __restrict__ a) {
    const int warp = threadIdx.x >> 5;
    const int lane = threadIdx.x & 31;
    const int row  = blockIdx.x * 8 + warp;
    const float* hr = g_h + (size_t)row * D_;
    float h0 = hr[lane], h1 = hr[lane + 32];
    float sl = h0 * a[lane]      + h1 * a[lane + 32];
    float sr = h0 * a[64 + lane] + h1 * a[96 + lane];
#pragma unroll
    for (int o = 16; o >= 1; o >>= 1) {
        sl += __shfl_xor_sync(0xffffffffu, sl, o);
        sr += __shfl_xor_sync(0xffffffffu, sr, o);
    }
    if (lane == 0) {
        g_rowA[row] = make_float4(expf(sl), expf(LRELU_A * sl), expf(-sl), sl);
        g_EBP[row]  = make_float2(expf(sr), expf(LRELU_A * sr));
    }
}

// ---------------------------------------------------------------------------
// Phase 2: fused attention, no exp in inner loop, no online softmax.
//   p_ij = adj ? ( EB_j > thr_i ? EA_i*EB_j : EA2_i*EB2_j ) : 0
//   acc[i] += p_ij * h[j]  (packed f32x2, 8x8 register blocking)
//   Each CTA handles RT=128 rows x JSL=2048 js; partial sums to global.
// ---------------------------------------------------------------------------
__global__ void __launch_bounds__(128) k_flash(const int* __restrict__ adj) {
    __shared__ __align__(16) float p_s[TJ][RT];   // transposed: [t][row] 32 KB
    __shared__ __align__(16) float h_s[TJ * D_];  // 16 KB

    const int tid = threadIdx.x;
    const int ib  = blockIdx.x & 63;
    const int sp  = blockIdx.x >> 6;
    const int i0  = ib * RT;
    const int jb  = sp * JSL;
    const int row = i0 + tid;

    const float4 rA  = g_rowA[row];
    const float  EA  = rA.x, EA2 = rA.y, thr = rA.z;

    const int rg = tid >> 3, cg = tid & 7;
    const int rbase = rg * 8, c0 = cg * 8;

    unsigned long long acc[4][8];
#pragma unroll
    for (int rp = 0; rp < 4; ++rp)
#pragma unroll
        for (int c = 0; c < 8; ++c) acc[rp][c] = 0ull;

    float rsum = 0.0f;
    const int4*   adjp = (const int4*)(adj + (size_t)row * N_ + jb);
    const float4* ebp  = (const float4*)(g_EBP + jb);   // float4 = 2x (EB,EB2)

    for (int tile = 0; tile < JSL / TJ; ++tile) {
        const int j0 = jb + tile * TJ;
        __syncthreads();   // prev acc done with p_s/h_s

        // cooperative h tile load (64 rows x 64 cols, contiguous)
        {
            const float4* src = (const float4*)(g_h + (size_t)j0 * D_);
            float4* dst = (float4*)h_s;
#pragma unroll
            for (int k = 0; k < 8; ++k) dst[tid + k * 128] = src[tid + k * 128];
        }

        // ---- e/p phase: this thread owns one full row, 64 js ----
#pragma unroll 4
        for (int q = 0; q < 16; ++q) {
            int4   m  = adjp[tile * 16 + q];
            float4 ea = ebp[tile * 32 + 2 * q];       // (EB,EB2, EB,EB2)
            float4 eb = ebp[tile * 32 + 2 * q + 1];
            float p0 = (ea.x > thr) ? EA * ea.x : EA2 * ea.y;  p0 = m.x ? p0 : 0.0f;
            float p1 = (ea.z > thr) ? EA * ea.z : EA2 * ea.w;  p1 = m.y ? p1 : 0.0f;
            float p2 = (eb.x > thr) ? EA * eb.x : EA2 * eb.y;  p2 = m.z ? p2 : 0.0f;
            float p3 = (eb.z > thr) ? EA * eb.z : EA2 * eb.w;  p3 = m.w ? p3 : 0.0f;
            rsum += p0 + p1 + p2 + p3;
            p_s[q * 4 + 0][tid] = p0;
            p_s[q * 4 + 1][tid] = p1;
            p_s[q * 4 + 2][tid] = p2;
            p_s[q * 4 + 3][tid] = p3;
        }
        __syncthreads();   // p_s / h_s visible

        // ---- acc phase: 8 rows x 8 cols per thread, packed f32x2 ----
#pragma unroll 4
        for (int t = 0; t < TJ; ++t) {
            ulonglong2 pq0 = *(const ulonglong2*)&p_s[t][rbase];      // rows +0..3
            ulonglong2 pq1 = *(const ulonglong2*)&p_s[t][rbase + 4];  // rows +4..7
            float4 h0 = *(const float4*)&h_s[t * D_ + c0];
            float4 h1 = *(const float4*)&h_s[t * D_ + c0 + 4];
            unsigned long long hd[8];
            hd[0] = pack2(h0.x); hd[1] = pack2(h0.y);
            hd[2] = pack2(h0.z); hd[3] = pack2(h0.w);
            hd[4] = pack2(h1.x); hd[5] = pack2(h1.y);
            hd[6] = pack2(h1.z); hd[7] = pack2(h1.w);
#pragma unroll
            for (int c = 0; c < 8; ++c) {
                acc[0][c] = fma2(pq0.x, hd[c], acc[0][c]);
                acc[1][c] = fma2(pq0.y, hd[c], acc[1][c]);
                acc[2][c] = fma2(pq1.x, hd[c], acc[2][c]);
                acc[3][c] = fma2(pq1.y, hd[c], acc[3][c]);
            }
        }
    }

    // ---- write partials ----
    g_psum[sp][row] = rsum;
#pragma unroll
    for (int rp = 0; rp < 4; ++rp) {
        const int r0 = i0 + rbase + rp * 2;   // even row of the pair
        float lo[8], hi[8];
#pragma unroll
        for (int c = 0; c < 8; ++c) {
            lo[c] = __uint_as_float((unsigned int)(acc[rp][c]));
            hi[c] = __uint_as_float((unsigned int)(acc[rp][c] >> 32));
        }
        *(float4*)&g_pacc[sp][r0][c0]         = make_float4(lo[0], lo[1], lo[2], lo[3]);
        *(float4*)&g_pacc[sp][r0][c0 + 4]     = make_float4(lo[4], lo[5], lo[6], lo[7]);
        *(float4*)&g_pacc[sp][r0 + 1][c0]     = make_float4(hi[0], hi[1], hi[2], hi[3]);
        *(float4*)&g_pacc[sp][r0 + 1][c0 + 4] = make_float4(hi[4], hi[5], hi[6], hi[7]);
    }
}

// ---------------------------------------------------------------------------
// Phase 3: combine partials, divide, ELU.
// ---------------------------------------------------------------------------
__global__ void __launch_bounds__(256) k_reduce(float* __restrict__ out) {
    const int idx = blockIdx.x * 256 + threadIdx.x;
    const int row = idx >> 4;
    const int c4  = (idx & 15) * 4;
    float4 s = make_float4(0.f, 0.f, 0.f, 0.f);
#pragma unroll
    for (int sp = 0; sp < JSPLIT; ++sp) {
        float4 v = *(const float4*)&g_pacc[sp][row][c4];
        s.x += v.x; s.y += v.y; s.z += v.z; s.w += v.w;
    }
    float den = g_psum[0][row] + g_psum[1][row] + g_psum[2][row] + g_psum[3][row];
    float inv = 1.0f / den;
    float v0 = s.x * inv, v1 = s.y * inv, v2 = s.z * inv, v3 = s.w * inv;
    v0 = (v0 > 0.f) ? v0 : expm1f(v0);
    v1 = (v1 > 0.f) ? v1 : expm1f(v1);
    v2 = (v2 > 0.f) ? v2 : expm1f(v2);
    v3 = (v3 > 0.f) ? v3 : expm1f(v3);
    *(float4*)(out + (size_t)row * D_ + c4) = make_float4(v0, v1, v2, v3);
}

// ---------------------------------------------------------------------------
extern "C" void kernel_launch(void* const* d_in, const int* in_sizes, int n_in,
                              void* d_out, int out_size) {
    const float* inp = (const float*)d_in[0];   // (8192, 512) f32
    const int*   adj = (const int*)d_in[1];     // (8192, 8192) i32
    const float* W   = (const float*)d_in[2];   // (512, 64) f32
    const float* a   = (const float*)d_in[3];   // (128, 1) f32
    float* out = (float*)d_out;                 // (8192, 64) f32

    k_gemm  <<<N_ / BM, 256>>>(inp, W);
    k_att   <<<N_ / 8,  256>>>(a);
    k_flash <<<(N_ / RT) * JSPLIT, 128>>>(adj);
    k_reduce<<<N_ * 16 / 256, 256>>>(out);
}

// round 8
// speedup vs baseline: 1.6223x; 1.1430x over previous
#include <cuda_runtime.h>
#include <math.h>

constexpr int N_    = 8192;
constexpr int IN_F_ = 512;
constexpr int D_    = 64;
constexpr float LRELU_A = 0.2f;

constexpr int RT     = 128;           // rows per flash CTA
constexpr int TJ     = 32;            // j-tile
constexpr int JSPLIT = 8;             // j-dimension split across CTAs
constexpr int JSL    = N_ / JSPLIT;   // 1024 j per CTA
constexpr int PSTR   = RT + 2;        // p_s row stride (130: keeps 8B align, 2-way max)

// Scratch (device globals; no allocation allowed)
__device__ __align__(16) float  g_h[N_ * D_];            // input @ W
__device__ __align__(16) float4 g_rowA[N_];              // (EA, EA2, thr=exp(-al), al)
__device__ __align__(16) float2 g_EBP[N_];               // (EB, EB2)
__device__ __align__(16) float  g_pacc[JSPLIT][N_][D_];  // partial acc (16.8 MB)
__device__ float g_psum[JSPLIT][N_];                     // partial softmax denom

// ---- packed f32x2 helpers ----
__device__ __forceinline__ unsigned long long fma2(unsigned long long a,
                                                   unsigned long long b,
                                                   unsigned long long c) {
    unsigned long long d;
    asm("fma.rn.f32x2 %0, %1, %2, %3;" : "=l"(d) : "l"(a), "l"(b), "l"(c));
    return d;
}
__device__ __forceinline__ unsigned long long pack2(float x) {
    unsigned long long d; unsigned int u = __float_as_uint(x);
    asm("mov.b64 %0, {%1, %1};" : "=l"(d) : "r"(u));
    return d;
}

// ---------------------------------------------------------------------------
// Phase 1: h = input @ W   (BM=32 -> grid 256, all SMs busy)
// ---------------------------------------------------------------------------
constexpr int BM = 32;
constexpr int BK = 32;

__global__ void __launch_bounds__(256) k_gemm(const float* __restrict__ inp,
                                              const float* __restrict__ W) {
    __shared__ float As[BK][BM + 1];
    __shared__ float Bs[BK][D_];
    const int tid  = threadIdx.x;
    const int row0 = blockIdx.x * BM;
    const int ty   = tid >> 4;         // 0..15 -> rows ty*2, ty*2+1
    const int tx   = tid & 15;         // cols tx*4..+3

    float acc[2][4];
#pragma unroll
    for (int i = 0; i < 2; ++i)
#pragma unroll
        for (int j = 0; j < 4; ++j) acc[i][j] = 0.0f;

    for (int k0 = 0; k0 < IN_F_; k0 += BK) {
        __syncthreads();
        {   // A tile: 32 rows x 32 k, transpose into As[k][row]
            const int r = tid >> 3;            // 0..31
            const int c = (tid & 7) * 4;       // 0..28
            float4 v = *(const float4*)(inp + (size_t)(row0 + r) * IN_F_ + k0 + c);
            As[c + 0][r] = v.x;
            As[c + 1][r] = v.y;
            As[c + 2][r] = v.z;
            As[c + 3][r] = v.w;
        }
        {   // B tile: 32 k x 64 cols
            const int kk = tid >> 3;
            const int c  = (tid & 7) * 8;
            float4 v0 = *(const float4*)(W + (size_t)(k0 + kk) * D_ + c);
            float4 v1 = *(const float4*)(W + (size_t)(k0 + kk) * D_ + c + 4);
            *(float4*)&Bs[kk][c]     = v0;
            *(float4*)&Bs[kk][c + 4] = v1;
        }
        __syncthreads();
#pragma unroll
        for (int kk = 0; kk < BK; ++kk) {
            float a0 = As[kk][ty * 2], a1 = As[kk][ty * 2 + 1];
            float4 b4 = *(const float4*)&Bs[kk][tx * 4];
            acc[0][0] += a0 * b4.x; acc[0][1] += a0 * b4.y;
            acc[0][2] += a0 * b4.z; acc[0][3] += a0 * b4.w;
            acc[1][0] += a1 * b4.x; acc[1][1] += a1 * b4.y;
            acc[1][2] += a1 * b4.z; acc[1][3] += a1 * b4.w;
        }
    }
#pragma unroll
    for (int i = 0; i < 2; ++i) {
        float4 v = make_float4(acc[i][0], acc[i][1], acc[i][2], acc[i][3]);
        *(float4*)(g_h + (size_t)(row0 + ty * 2 + i) * D_ + tx * 4) = v;
    }
}

// ---------------------------------------------------------------------------
// Phase 1b: per-node attention scalars + exponentials.
// ---------------------------------------------------------------------------
__global__ void __launch_bounds__(256) k_att(const float* __restrict__ a) {
    const int warp = threadIdx.x >> 5;
    const int lane = threadIdx.x & 31;
    const int row  = blockIdx.x * 8 + warp;
    const float* hr = g_h + (size_t)row * D_;
    float h0 = hr[lane], h1 = hr[lane + 32];
    float sl = h0 * a[lane]      + h1 * a[lane + 32];
    float sr = h0 * a[64 + lane] + h1 * a[96 + lane];
#pragma unroll
    for (int o = 16; o >= 1; o >>= 1) {
        sl += __shfl_xor_sync(0xffffffffu, sl, o);
        sr += __shfl_xor_sync(0xffffffffu, sr, o);
    }
    if (lane == 0) {
        g_rowA[row] = make_float4(expf(sl), expf(LRELU_A * sl), expf(-sl), sl);
        g_EBP[row]  = make_float2(expf(sr), expf(LRELU_A * sr));
    }
}

// ---------------------------------------------------------------------------
// Phase 2: fused attention.
//   p_ij = adj ? ( EB_j > thr_i ? EA_i*EB_j : EA2_i*EB2_j ) : 0
//   e-phase: warp covers 4 rows x 32 j per step (coalesced adj: 4 lines/LDG)
//   acc-phase: 8 rows x 8 cols per thread, packed f32x2
// ---------------------------------------------------------------------------
__global__ void __launch_bounds__(128, 4) k_flash(const int* __restrict__ adj) {
    __shared__ __align__(16) float  p_s[TJ][PSTR];  // transposed probs, 16.6 KB
    __shared__ __align__(16) float  h_s[TJ * D_];   // 8 KB
    __shared__ __align__(16) float4 rA_s[RT];       // 2 KB
    __shared__ float s_s[RT];                       // per-row softmax denom

    const int tid = threadIdx.x;
    const int ib  = blockIdx.x & 63;
    const int sp  = blockIdx.x >> 6;                // 0..7
    const int i0  = ib * RT;
    const int jb  = sp * JSL;

    rA_s[tid] = g_rowA[i0 + tid];
    s_s[tid]  = 0.0f;

    // e-phase lane mapping
    const int w    = tid >> 5;          // warp 0..3
    const int lane = tid & 31;
    const int sub  = lane >> 3;         // 0..3: row within warp-group
    const int l8   = lane & 7;          // 0..7: j-group (4 j each)

    // acc-phase mapping
    const int rg = tid >> 3, cg = tid & 7;
    const int rbase = rg * 8, c0 = cg * 8;

    unsigned long long acc[4][8];
#pragma unroll
    for (int rp = 0; rp < 4; ++rp)
#pragma unroll
        for (int c = 0; c < 8; ++c) acc[rp][c] = 0ull;

    const float4* ebp = (const float4*)(g_EBP + jb);   // float4 = 2x (EB,EB2)

    for (int tile = 0; tile < JSL / TJ; ++tile) {
        const int j0 = jb + tile * TJ;
        __syncthreads();   // prev acc done with p_s/h_s

        // cooperative h tile load (32 rows x 64 cols, contiguous)
        {
            const float4* src = (const float4*)(g_h + (size_t)j0 * D_);
            float4* dst = (float4*)h_s;
#pragma unroll
            for (int k = 0; k < 4; ++k) dst[tid + k * 128] = src[tid + k * 128];
        }

        // ---- e/p phase: 8 steps, each warp does 4 rows x 32 j ----
        // lane's ebp: j = l8*4 .. l8*4+3  -> float4 idx tile*16 + 2*l8 (+1)
        const float4 ea = ebp[tile * 16 + 2 * l8];
        const float4 eb = ebp[tile * 16 + 2 * l8 + 1];
#pragma unroll 2
        for (int it = 0; it < 8; ++it) {
            const int row = it * 16 + w * 4 + sub;         // 0..127
            const float4 rv = rA_s[row];                   // EA, EA2, thr
            const float EA = rv.x, EA2 = rv.y, thr = rv.z;
            int4 m = *(const int4*)(adj + (size_t)(i0 + row) * N_ + j0 + l8 * 4);
            float p0 = (ea.x > thr) ? EA * ea.x : EA2 * ea.y;  p0 = m.x ? p0 : 0.0f;
            float p1 = (ea.z > thr) ? EA * ea.z : EA2 * ea.w;  p1 = m.y ? p1 : 0.0f;
            float p2 = (eb.x > thr) ? EA * eb.x : EA2 * eb.y;  p2 = m.z ? p2 : 0.0f;
            float p3 = (eb.z > thr) ? EA * eb.z : EA2 * eb.w;  p3 = m.w ? p3 : 0.0f;
            p_s[l8 * 4 + 0][row] = p0;
            p_s[l8 * 4 + 1][row] = p1;
            p_s[l8 * 4 + 2][row] = p2;
            p_s[l8 * 4 + 3][row] = p3;
            float rs = p0 + p1 + p2 + p3;
#pragma unroll
            for (int o = 4; o >= 1; o >>= 1)                // reduce over l8 group
                rs += __shfl_xor_sync(0xffffffffu, rs, o);
            if (l8 == 0) s_s[row] += rs;
        }
        __syncthreads();   // p_s / h_s / s_s visible

        // ---- acc phase: 8 rows x 8 cols per thread, packed f32x2 ----
#pragma unroll 4
        for (int t = 0; t < TJ; ++t) {
            const float* pr = &p_s[t][rbase];
            unsigned long long pq0 = *(const unsigned long long*)(pr);      // rows +0,1
            unsigned long long pq1 = *(const unsigned long long*)(pr + 2);  // rows +2,3
            unsigned long long pq2 = *(const unsigned long long*)(pr + 4);
            unsigned long long pq3 = *(const unsigned long long*)(pr + 6);
            float4 h0 = *(const float4*)&h_s[t * D_ + c0];
            float4 h1 = *(const float4*)&h_s[t * D_ + c0 + 4];
            unsigned long long hd[8];
            hd[0] = pack2(h0.x); hd[1] = pack2(h0.y);
            hd[2] = pack2(h0.z); hd[3] = pack2(h0.w);
            hd[4] = pack2(h1.x); hd[5] = pack2(h1.y);
            hd[6] = pack2(h1.z); hd[7] = pack2(h1.w);
#pragma unroll
            for (int c = 0; c < 8; ++c) {
                acc[0][c] = fma2(pq0, hd[c], acc[0][c]);
                acc[1][c] = fma2(pq1, hd[c], acc[1][c]);
                acc[2][c] = fma2(pq2, hd[c], acc[2][c]);
                acc[3][c] = fma2(pq3, hd[c], acc[3][c]);
            }
        }
    }
    __syncthreads();

    // ---- write partials ----
    g_psum[sp][i0 + tid] = s_s[tid];
#pragma unroll
    for (int rp = 0; rp < 4; ++rp) {
        const int r0 = i0 + rbase + rp * 2;   // even row of the pair
        float lo[8], hi[8];
#pragma unroll
        for (int c = 0; c < 8; ++c) {
            lo[c] = __uint_as_float((unsigned int)(acc[rp][c]));
            hi[c] = __uint_as_float((unsigned int)(acc[rp][c] >> 32));
        }
        *(float4*)&g_pacc[sp][r0][c0]         = make_float4(lo[0], lo[1], lo[2], lo[3]);
        *(float4*)&g_pacc[sp][r0][c0 + 4]     = make_float4(lo[4], lo[5], lo[6], lo[7]);
        *(float4*)&g_pacc[sp][r0 + 1][c0]     = make_float4(hi[0], hi[1], hi[2], hi[3]);
        *(float4*)&g_pacc[sp][r0 + 1][c0 + 4] = make_float4(hi[4], hi[5], hi[6], hi[7]);
    }
}

// ---------------------------------------------------------------------------
// Phase 3: combine partials, divide, ELU.
// ---------------------------------------------------------------------------
__global__ void __launch_bounds__(256) k_reduce(float* __restrict__ out) {
    const int idx = blockIdx.x * 256 + threadIdx.x;
    const int row = idx >> 4;
    const int c4  = (idx & 15) * 4;
    float4 s = make_float4(0.f, 0.f, 0.f, 0.f);
    float den = 0.0f;
#pragma unroll
    for (int sp = 0; sp < JSPLIT; ++sp) {
        float4 v = *(const float4*)&g_pacc[sp][row][c4];
        s.x += v.x; s.y += v.y; s.z += v.z; s.w += v.w;
        den += g_psum[sp][row];
    }
    float inv = 1.0f / den;
    float v0 = s.x * inv, v1 = s.y * inv, v2 = s.z * inv, v3 = s.w * inv;
    v0 = (v0 > 0.f) ? v0 : expm1f(v0);
    v1 = (v1 > 0.f) ? v1 : expm1f(v1);
    v2 = (v2 > 0.f) ? v2 : expm1f(v2);
    v3 = (v3 > 0.f) ? v3 : expm1f(v3);
    *(float4*)(out + (size_t)row * D_ + c4) = make_float4(v0, v1, v2, v3);
}

// ---------------------------------------------------------------------------
extern "C" void kernel_launch(void* const* d_in, const int* in_sizes, int n_in,
                              void* d_out, int out_size) {
    const float* inp = (const float*)d_in[0];   // (8192, 512) f32
    const int*   adj = (const int*)d_in[1];     // (8192, 8192) i32
    const float* W   = (const float*)d_in[2];   // (512, 64) f32
    const float* a   = (const float*)d_in[3];   // (128, 1) f32
    float* out = (float*)d_out;                 // (8192, 64) f32

    k_gemm  <<<N_ / BM, 256>>>(inp, W);
    k_att   <<<N_ / 8,  256>>>(a);
    k_flash <<<(N_ / RT) * JSPLIT, 128>>>(adj);
    k_reduce<<<N_ * 16 / 256, 256>>>(out);
}

// round 15
// speedup vs baseline: 2.4506x; 1.5105x over previous
#include <cuda_runtime.h>
#include <cuda_bf16.h>
#include <mma.h>
#include <math.h>
#include <stdint.h>

using namespace nvcuda;

constexpr int N_    = 8192;
constexpr int IN_F_ = 512;
constexpr int D_    = 64;
constexpr float LRELU_A = 0.2f;

constexpr int RTF    = 128;           // rows per flash CTA
constexpr int TJ     = 64;            // j-tile (K per mma group)
constexpr int JSPLIT = 4;
constexpr int JSL    = N_ / JSPLIT;   // 2048
constexpr int NTILES = JSL / TJ;      // 32

// smem layout (bytes from dynamic base; bf16 rows padded to 72 elems = 144B)
constexpr int PHI = 0;                 // P hi  [128][72] bf16 = 18432
constexpr int PLO = 18432;             // P lo
constexpr int HHI = 36864;             // H^T hi [64][72] bf16 = 9216
constexpr int HLO = 46080;             // H^T lo
constexpr int RAO = 55296;             // rowA float4[128] = 2048
constexpr int SSO = 57344;             // row sums float[128]
constexpr int SMEM_DYN = 57856;

// ---- device scratch ----
__device__ __align__(16) float  g_h[N_ * D_];
__device__ __align__(16) float4 g_rowA[N_];              // (EA, EA2, thr, al)
__device__ __align__(16) float2 g_EBP[N_];               // (EB, EB2)
__device__ __align__(16) __nv_bfloat16 g_hThi[D_ * N_];  // H^T hi  [n][j]
__device__ __align__(16) __nv_bfloat16 g_hTlo[D_ * N_];  // H^T lo
__device__ __align__(16) float  g_pacc[JSPLIT][N_][D_];
__device__ float g_psum[JSPLIT][N_];

__device__ __forceinline__ uint32_t cvt_bf16x2(float lo, float hi) {
    uint32_t r;
    asm("cvt.rn.bf16x2.f32 %0, %2, %1;" : "=r"(r) : "f"(lo), "f"(hi));
    return r;
}

// ---------------------------------------------------------------------------
// Phase 1: h = input @ W   (unchanged, passing since R8)
// ---------------------------------------------------------------------------
constexpr int BM = 32;
constexpr int BK = 32;

__global__ void __launch_bounds__(256) k_gemm(const float* __restrict__ inp,
                                              const float* __restrict__ W) {
    __shared__ float As[BK][BM + 1];
    __shared__ float Bs[BK][D_];
    const int tid  = threadIdx.x;
    const int row0 = blockIdx.x * BM;
    const int ty   = tid >> 4;
    const int tx   = tid & 15;

    float acc[2][4];
#pragma unroll
    for (int i = 0; i < 2; ++i)
#pragma unroll
        for (int j = 0; j < 4; ++j) acc[i][j] = 0.0f;

    for (int k0 = 0; k0 < IN_F_; k0 += BK) {
        __syncthreads();
        {
            const int r = tid >> 3;
            const int c = (tid & 7) * 4;
            float4 v = *(const float4*)(inp + (size_t)(row0 + r) * IN_F_ + k0 + c);
            As[c + 0][r] = v.x; As[c + 1][r] = v.y;
            As[c + 2][r] = v.z; As[c + 3][r] = v.w;
        }
        {
            const int kk = tid >> 3;
            const int c  = (tid & 7) * 8;
            float4 v0 = *(const float4*)(W + (size_t)(k0 + kk) * D_ + c);
            float4 v1 = *(const float4*)(W + (size_t)(k0 + kk) * D_ + c + 4);
            *(float4*)&Bs[kk][c]     = v0;
            *(float4*)&Bs[kk][c + 4] = v1;
        }
        __syncthreads();
#pragma unroll
        for (int kk = 0; kk < BK; ++kk) {
            float a0 = As[kk][ty * 2], a1 = As[kk][ty * 2 + 1];
            float4 b4 = *(const float4*)&Bs[kk][tx * 4];
            acc[0][0] += a0 * b4.x; acc[0][1] += a0 * b4.y;
            acc[0][2] += a0 * b4.z; acc[0][3] += a0 * b4.w;
            acc[1][0] += a1 * b4.x; acc[1][1] += a1 * b4.y;
            acc[1][2] += a1 * b4.z; acc[1][3] += a1 * b4.w;
        }
    }
#pragma unroll
    for (int i = 0; i < 2; ++i) {
        float4 v = make_float4(acc[i][0], acc[i][1], acc[i][2], acc[i][3]);
        *(float4*)(g_h + (size_t)(row0 + ty * 2 + i) * D_ + tx * 4) = v;
    }
}

// ---------------------------------------------------------------------------
// Phase 1b: per-node attention scalars + exponentials.
// ---------------------------------------------------------------------------
__global__ void __launch_bounds__(256) k_att(const float* __restrict__ a) {
    const int warp = threadIdx.x >> 5;
    const int lane = threadIdx.x & 31;
    const int row  = blockIdx.x * 8 + warp;
    const float* hr = g_h + (size_t)row * D_;
    float h0 = hr[lane], h1 = hr[lane + 32];
    float sl = h0 * a[lane]      + h1 * a[lane + 32];
    float sr = h0 * a[64 + lane] + h1 * a[96 + lane];
#pragma unroll
    for (int o = 16; o >= 1; o >>= 1) {
        sl += __shfl_xor_sync(0xffffffffu, sl, o);
        sr += __shfl_xor_sync(0xffffffffu, sr, o);
    }
    if (lane == 0) {
        g_rowA[row] = make_float4(expf(sl), expf(LRELU_A * sl), expf(-sl), sl);
        g_EBP[row]  = make_float2(expf(sr), expf(LRELU_A * sr));
    }
}

// ---------------------------------------------------------------------------
// Phase 1c: H^T hi/lo bf16 split  (g_hThi/lo[n][j] = split of g_h[j][n])
// ---------------------------------------------------------------------------
__global__ void __launch_bounds__(256) k_hT() {
    __shared__ float ts[64][65];
    const int j0  = blockIdx.x * 64;
    const int tid = threadIdx.x;
#pragma unroll
    for (int i = 0; i < 4; ++i) {
        int idx = tid + i * 256;
        int r = idx >> 4, c4 = (idx & 15) * 4;
        float4 v = *(const float4*)(g_h + (size_t)(j0 + r) * D_ + c4);
        ts[r][c4] = v.x; ts[r][c4 + 1] = v.y; ts[r][c4 + 2] = v.z; ts[r][c4 + 3] = v.w;
    }
    __syncthreads();
#pragma unroll
    for (int i = 0; i < 16; ++i) {
        int idx = tid + i * 256;
        int n = idx >> 6, jl = idx & 63;
        float h = ts[jl][n];
        __nv_bfloat16 hi = __float2bfloat16(h);
        float lo = h - __bfloat162float(hi);
        g_hThi[(size_t)n * N_ + j0 + jl] = hi;
        g_hTlo[(size_t)n * N_ + j0 + jl] = __float2bfloat16(lo);
    }
}

// ---------------------------------------------------------------------------
// Phase 2: WMMA bf16 flash.  D(128x64 f32) += Phi*Hhi + Phi*Hlo + Plo*Hhi
// ---------------------------------------------------------------------------
__global__ void __launch_bounds__(256) k_flash(const int* __restrict__ adj) {
    extern __shared__ char sm[];
    __nv_bfloat16* Phi = (__nv_bfloat16*)(sm + PHI);
    __nv_bfloat16* Plo = (__nv_bfloat16*)(sm + PLO);
    __nv_bfloat16* Hhi = (__nv_bfloat16*)(sm + HHI);
    __nv_bfloat16* Hlo = (__nv_bfloat16*)(sm + HLO);
    float4* rA = (float4*)(sm + RAO);
    float*  ss = (float*)(sm + SSO);

    const int tid  = threadIdx.x;
    const int wid  = tid >> 5;
    const int lane = tid & 31;
    const int ib   = blockIdx.x & 63;
    const int sp   = blockIdx.x >> 6;
    const int i0   = ib * RTF;
    const int jb   = sp * JSL;

    if (tid < RTF) {
        rA[tid] = g_rowA[i0 + tid];
        ss[tid] = 0.0f;
    }

    wmma::fragment<wmma::accumulator, 16, 16, 16, float> acc[4];
#pragma unroll
    for (int n = 0; n < 4; ++n) wmma::fill_fragment(acc[n], 0.0f);

    const int sub = lane >> 3;     // row-within-warp-group
    const int l8  = lane & 7;      // j-chunk of 4
    const float4* ebp = (const float4*)(g_EBP + jb);

    for (int t = 0; t < NTILES; ++t) {
        const int jg = jb + t * TJ;
        __syncthreads();   // prev mma done with smem

        // ---- H^T tiles (hi+lo): 64 n x 64 k bf16 each ----
#pragma unroll
        for (int rep = 0; rep < 2; ++rep) {
            int idx = tid + rep * 256;       // 0..511
            int n = idx >> 3, u = idx & 7;   // 8 bf16 per chunk
            int4 vh = *(const int4*)(g_hThi + (size_t)n * N_ + jg + u * 8);
            int4 vl = *(const int4*)(g_hTlo + (size_t)n * N_ + jg + u * 8);
            *(int4*)((char*)Hhi + n * 144 + u * 16) = vh;
            *(int4*)((char*)Hlo + n * 144 + u * 16) = vl;
        }

        // ---- P tiles: warp covers 4 rows x 64 j per pass, 4 passes ----
#pragma unroll
        for (int it = 0; it < 4; ++it) {
            const int row = it * 32 + wid * 4 + sub;
            const float4 rv = rA[row];
            const float EA = rv.x, EA2 = rv.y, thr = rv.z;
            float rs = 0.0f;
#pragma unroll
            for (int q = 0; q < 2; ++q) {
                const int j = q * 32 + l8 * 4;
                int4 m = *(const int4*)(adj + (size_t)(i0 + row) * N_ + jg + j);
                float4 ea = ebp[t * 32 + (j >> 1)];
                float4 eb = ebp[t * 32 + (j >> 1) + 1];
                float p0 = (ea.x > thr) ? EA * ea.x : EA2 * ea.y;  p0 = m.x ? p0 : 0.0f;
                float p1 = (ea.z > thr) ? EA * ea.z : EA2 * ea.w;  p1 = m.y ? p1 : 0.0f;
                float p2 = (eb.x > thr) ? EA * eb.x : EA2 * eb.y;  p2 = m.z ? p2 : 0.0f;
                float p3 = (eb.z > thr) ? EA * eb.z : EA2 * eb.w;  p3 = m.w ? p3 : 0.0f;
                rs += p0 + p1 + p2 + p3;
                uint32_t h01 = cvt_bf16x2(p0, p1);
                uint32_t h23 = cvt_bf16x2(p2, p3);
                float l0 = p0 - __uint_as_float(h01 << 16);
                float l1 = p1 - __uint_as_float(h01 & 0xFFFF0000u);
                float l2 = p2 - __uint_as_float(h23 << 16);
                float l3 = p3 - __uint_as_float(h23 & 0xFFFF0000u);
                uint32_t q01 = cvt_bf16x2(l0, l1);
                uint32_t q23 = cvt_bf16x2(l2, l3);
                *(uint2*)((char*)Phi + row * 144 + j * 2) = make_uint2(h01, h23);
                *(uint2*)((char*)Plo + row * 144 + j * 2) = make_uint2(q01, q23);
            }
#pragma unroll
            for (int o = 4; o >= 1; o >>= 1)
                rs += __shfl_xor_sync(0xffffffffu, rs, o);
            if (l8 == 0) ss[row] += rs;
        }
        __syncthreads();   // P/H tiles visible

        // ---- mma phase: warp owns rows wid*16..+15, all 64 cols ----
        const __nv_bfloat16* pw_hi = Phi + wid * 16 * 72;
        const __nv_bfloat16* pw_lo = Plo + wid * 16 * 72;
#pragma unroll
        for (int k = 0; k < 4; ++k) {
            wmma::fragment<wmma::matrix_a, 16, 16, 16, __nv_bfloat16, wmma::row_major> ahi, alo;
            wmma::load_matrix_sync(ahi, pw_hi + k * 16, 72);
            wmma::load_matrix_sync(alo, pw_lo + k * 16, 72);
#pragma unroll
            for (int n = 0; n < 4; ++n) {
                wmma::fragment<wmma::matrix_b, 16, 16, 16, __nv_bfloat16, wmma::col_major> bhi, blo;
                wmma::load_matrix_sync(bhi, Hhi + n * 16 * 72 + k * 16, 72);
                wmma::load_matrix_sync(blo, Hlo + n * 16 * 72 + k * 16, 72);
                wmma::mma_sync(acc[n], ahi, bhi, acc[n]);
                wmma::mma_sync(acc[n], ahi, blo, acc[n]);
                wmma::mma_sync(acc[n], alo, bhi, acc[n]);
            }
        }
    }
    __syncthreads();

    // ---- epilogue: partial sums to global ----
    if (tid < RTF) g_psum[sp][i0 + tid] = ss[tid];
#pragma unroll
    for (int n = 0; n < 4; ++n)
        wmma::store_matrix_sync(&g_pacc[sp][i0 + wid * 16][n * 16], acc[n], 64,
                                wmma::mem_row_major);
}

// ---------------------------------------------------------------------------
// Phase 3: combine partials, divide, ELU.
// ---------------------------------------------------------------------------
__global__ void __launch_bounds__(256) k_reduce(float* __restrict__ out) {
    const int idx = blockIdx.x * 256 + threadIdx.x;
    const int row = idx >> 4;
    const int c4  = (idx & 15) * 4;
    float4 s = make_float4(0.f, 0.f, 0.f, 0.f);
    float den = 0.0f;
#pragma unroll
    for (int sp = 0; sp < JSPLIT; ++sp) {
        float4 v = *(const float4*)&g_pacc[sp][row][c4];
        s.x += v.x; s.y += v.y; s.z += v.z; s.w += v.w;
        den += g_psum[sp][row];
    }
    float inv = 1.0f / den;
    float v0 = s.x * inv, v1 = s.y * inv, v2 = s.z * inv, v3 = s.w * inv;
    v0 = (v0 > 0.f) ? v0 : expm1f(v0);
    v1 = (v1 > 0.f) ? v1 : expm1f(v1);
    v2 = (v2 > 0.f) ? v2 : expm1f(v2);
    v3 = (v3 > 0.f) ? v3 : expm1f(v3);
    *(float4*)(out + (size_t)row * D_ + c4) = make_float4(v0, v1, v2, v3);
}

// ---------------------------------------------------------------------------
extern "C" void kernel_launch(void* const* d_in, const int* in_sizes, int n_in,
                              void* d_out, int out_size) {
    const float* inp = (const float*)d_in[0];   // (8192, 512) f32
    const int*   adj = (const int*)d_in[1];     // (8192, 8192) i32
    const float* W   = (const float*)d_in[2];   // (512, 64) f32
    const float* a   = (const float*)d_in[3];   // (128, 1) f32
    float* out = (float*)d_out;                 // (8192, 64) f32

    cudaFuncSetAttribute(k_flash, cudaFuncAttributeMaxDynamicSharedMemorySize, SMEM_DYN);

    k_gemm  <<<N_ / BM, 256>>>(inp, W);
    k_att   <<<N_ / 8,  256>>>(a);
    k_hT    <<<N_ / 64, 256>>>();
    k_flash <<<(N_ / RTF) * JSPLIT, 256, SMEM_DYN>>>(adj);
    k_reduce<<<N_ * 16 / 256, 256>>>(out);
}